// round 1
// baseline (speedup 1.0000x reference)
#include <cuda_runtime.h>
#include <math_constants.h>

// SparseSelfAttention: B=2,H=16,L=2048,D=64,BLK=32,NB=64, causal-local window=8 blocks
// Inputs (metadata order): query f32 [B,H,L,D], key f32, value f32,
//   key_padding_mask f32 [B,L], layout i32 [H,NB,NB]. Output f32 [B,H,L,D].

#define HEADS 16
#define SEQ   2048
#define DIM   64
#define NB    64
#define BLK   32

__global__ __launch_bounds__(128, 4)
void sparse_attn_kernel(const float* __restrict__ qg,
                        const float* __restrict__ kg,
                        const float* __restrict__ vg,
                        const float* __restrict__ kpm,
                        const int*   __restrict__ layout,
                        float* __restrict__ outg)
{
    // padded smem: row stride 68 floats (272B) -> conflict-free float4 reads
    __shared__ float Qs[BLK][68];
    __shared__ float Ks[BLK][68];
    __shared__ float Vs[BLK][68];
    __shared__ float Ps[BLK][33];
    __shared__ float kpms[BLK];
    __shared__ int   lay[NB];

    const int i   = blockIdx.x;   // query block row
    const int h   = blockIdx.y;
    const int b   = blockIdx.z;
    const int tid = threadIdx.x;  // 0..127
    const int g     = tid >> 3;   // row group 0..15
    const int lane8 = tid & 7;
    const int r0 = 2 * g;
    const int r1 = 2 * g + 1;

    const size_t bh = (size_t)b * HEADS + h;
    const float* qptr = qg + (bh * SEQ + (size_t)i * BLK) * DIM;
    const float* kbase = kg + bh * SEQ * DIM;
    const float* vbase = vg + bh * SEQ * DIM;
    float* optr = outg + (bh * SEQ + (size_t)i * BLK) * DIM;

    if (tid < NB) lay[tid] = layout[(h * NB + i) * NB + tid];

    // load Q block: 32x64 f32 = 512 float4
    #pragma unroll
    for (int jj = 0; jj < 4; jj++) {
        int idx = tid + 128 * jj;
        int row = idx >> 4, d4 = idx & 15;
        float4 val = reinterpret_cast<const float4*>(qptr)[idx];
        *(reinterpret_cast<float4*>(&Qs[row][0]) + d4) = val;
    }
    __syncthreads();

    float m0 = -CUDART_INF_F, m1 = -CUDART_INF_F;
    float l0 = 0.f, l1 = 0.f;
    float4 o00 = {0,0,0,0}, o01 = {0,0,0,0};  // row r0, dim chunks lane8, lane8+8
    float4 o10 = {0,0,0,0}, o11 = {0,0,0,0};  // row r1

    const float scale = 0.125f;  // 64^-0.5

    for (int j = 0; j < NB; j++) {
        if (!lay[j]) continue;

        // load K/V block j (+ key padding mask slice)
        const float* kp = kbase + (size_t)j * BLK * DIM;
        const float* vp = vbase + (size_t)j * BLK * DIM;
        #pragma unroll
        for (int jj = 0; jj < 4; jj++) {
            int idx = tid + 128 * jj;
            int row = idx >> 4, d4 = idx & 15;
            float4 kv4 = reinterpret_cast<const float4*>(kp)[idx];
            float4 vv4 = reinterpret_cast<const float4*>(vp)[idx];
            *(reinterpret_cast<float4*>(&Ks[row][0]) + d4) = kv4;
            *(reinterpret_cast<float4*>(&Vs[row][0]) + d4) = vv4;
        }
        if (tid < BLK) kpms[tid] = kpm[b * SEQ + j * BLK + tid];
        __syncthreads();

        // QK^T: thread computes s[2 rows][4 k-cols], k = lane8 + 8*kk
        float s00 = 0.f, s01 = 0.f, s02 = 0.f, s03 = 0.f;
        float s10 = 0.f, s11 = 0.f, s12 = 0.f, s13 = 0.f;
        #pragma unroll
        for (int d4 = 0; d4 < 16; d4++) {
            float4 q0 = *(reinterpret_cast<const float4*>(&Qs[r0][0]) + d4);
            float4 q1 = *(reinterpret_cast<const float4*>(&Qs[r1][0]) + d4);
            float4 k0 = *(reinterpret_cast<const float4*>(&Ks[lane8     ][0]) + d4);
            float4 k1 = *(reinterpret_cast<const float4*>(&Ks[lane8 +  8][0]) + d4);
            float4 k2 = *(reinterpret_cast<const float4*>(&Ks[lane8 + 16][0]) + d4);
            float4 k3 = *(reinterpret_cast<const float4*>(&Ks[lane8 + 24][0]) + d4);
            s00 = fmaf(q0.x,k0.x, fmaf(q0.y,k0.y, fmaf(q0.z,k0.z, fmaf(q0.w,k0.w, s00))));
            s01 = fmaf(q0.x,k1.x, fmaf(q0.y,k1.y, fmaf(q0.z,k1.z, fmaf(q0.w,k1.w, s01))));
            s02 = fmaf(q0.x,k2.x, fmaf(q0.y,k2.y, fmaf(q0.z,k2.z, fmaf(q0.w,k2.w, s02))));
            s03 = fmaf(q0.x,k3.x, fmaf(q0.y,k3.y, fmaf(q0.z,k3.z, fmaf(q0.w,k3.w, s03))));
            s10 = fmaf(q1.x,k0.x, fmaf(q1.y,k0.y, fmaf(q1.z,k0.z, fmaf(q1.w,k0.w, s10))));
            s11 = fmaf(q1.x,k1.x, fmaf(q1.y,k1.y, fmaf(q1.z,k1.z, fmaf(q1.w,k1.w, s11))));
            s12 = fmaf(q1.x,k2.x, fmaf(q1.y,k2.y, fmaf(q1.z,k2.z, fmaf(q1.w,k2.w, s12))));
            s13 = fmaf(q1.x,k3.x, fmaf(q1.y,k3.y, fmaf(q1.z,k3.z, fmaf(q1.w,k3.w, s13))));
        }

        // scale + key padding bias
        float kb0 = kpms[lane8], kb1 = kpms[lane8+8], kb2 = kpms[lane8+16], kb3 = kpms[lane8+24];
        s00 = fmaf(s00, scale, kb0); s01 = fmaf(s01, scale, kb1);
        s02 = fmaf(s02, scale, kb2); s03 = fmaf(s03, scale, kb3);
        s10 = fmaf(s10, scale, kb0); s11 = fmaf(s11, scale, kb1);
        s12 = fmaf(s12, scale, kb2); s13 = fmaf(s13, scale, kb3);

        // row max across this block (4 local + 8-lane shfl groups)
        float bm0 = fmaxf(fmaxf(s00, s01), fmaxf(s02, s03));
        float bm1 = fmaxf(fmaxf(s10, s11), fmaxf(s12, s13));
        #pragma unroll
        for (int off = 1; off < 8; off <<= 1) {
            bm0 = fmaxf(bm0, __shfl_xor_sync(0xffffffffu, bm0, off));
            bm1 = fmaxf(bm1, __shfl_xor_sync(0xffffffffu, bm1, off));
        }
        float mn0 = fmaxf(m0, bm0);
        float mn1 = fmaxf(m1, bm1);
        float a0 = __expf(m0 - mn0);   // 0 on first active block
        float a1 = __expf(m1 - mn1);
        m0 = mn0; m1 = mn1;

        float p00 = __expf(s00 - mn0), p01 = __expf(s01 - mn0);
        float p02 = __expf(s02 - mn0), p03 = __expf(s03 - mn0);
        float p10 = __expf(s10 - mn1), p11 = __expf(s11 - mn1);
        float p12 = __expf(s12 - mn1), p13 = __expf(s13 - mn1);

        float ls0 = p00 + p01 + p02 + p03;
        float ls1 = p10 + p11 + p12 + p13;
        #pragma unroll
        for (int off = 1; off < 8; off <<= 1) {
            ls0 += __shfl_xor_sync(0xffffffffu, ls0, off);
            ls1 += __shfl_xor_sync(0xffffffffu, ls1, off);
        }
        l0 = l0 * a0 + ls0;
        l1 = l1 * a1 + ls1;

        // rescale accumulators
        o00.x *= a0; o00.y *= a0; o00.z *= a0; o00.w *= a0;
        o01.x *= a0; o01.y *= a0; o01.z *= a0; o01.w *= a0;
        o10.x *= a1; o10.y *= a1; o10.z *= a1; o10.w *= a1;
        o11.x *= a1; o11.y *= a1; o11.z *= a1; o11.w *= a1;

        // publish probabilities
        Ps[r0][lane8     ] = p00; Ps[r0][lane8 +  8] = p01;
        Ps[r0][lane8 + 16] = p02; Ps[r0][lane8 + 24] = p03;
        Ps[r1][lane8     ] = p10; Ps[r1][lane8 +  8] = p11;
        Ps[r1][lane8 + 16] = p12; Ps[r1][lane8 + 24] = p13;
        __syncthreads();

        // PV: o[r][chunk] += sum_k P[r][k] * V[k][chunk]
        #pragma unroll 4
        for (int kk = 0; kk < BLK; kk++) {
            float pa = Ps[r0][kk];
            float pb = Ps[r1][kk];
            float4 v0 = *(reinterpret_cast<const float4*>(&Vs[kk][0]) + lane8);
            float4 v1 = *(reinterpret_cast<const float4*>(&Vs[kk][0]) + lane8 + 8);
            o00.x = fmaf(pa, v0.x, o00.x); o00.y = fmaf(pa, v0.y, o00.y);
            o00.z = fmaf(pa, v0.z, o00.z); o00.w = fmaf(pa, v0.w, o00.w);
            o01.x = fmaf(pa, v1.x, o01.x); o01.y = fmaf(pa, v1.y, o01.y);
            o01.z = fmaf(pa, v1.z, o01.z); o01.w = fmaf(pa, v1.w, o01.w);
            o10.x = fmaf(pb, v0.x, o10.x); o10.y = fmaf(pb, v0.y, o10.y);
            o10.z = fmaf(pb, v0.z, o10.z); o10.w = fmaf(pb, v0.w, o10.w);
            o11.x = fmaf(pb, v1.x, o11.x); o11.y = fmaf(pb, v1.y, o11.y);
            o11.z = fmaf(pb, v1.z, o11.z); o11.w = fmaf(pb, v1.w, o11.w);
        }
        __syncthreads();  // protect Ks/Vs/Ps before next block's loads
    }

    // final normalize + store
    float inv0 = 1.0f / l0;
    float inv1 = 1.0f / l1;
    o00.x *= inv0; o00.y *= inv0; o00.z *= inv0; o00.w *= inv0;
    o01.x *= inv0; o01.y *= inv0; o01.z *= inv0; o01.w *= inv0;
    o10.x *= inv1; o10.y *= inv1; o10.z *= inv1; o10.w *= inv1;
    o11.x *= inv1; o11.y *= inv1; o11.z *= inv1; o11.w *= inv1;

    float4* out4 = reinterpret_cast<float4*>(optr);
    out4[r0 * 16 + lane8    ] = o00;
    out4[r0 * 16 + lane8 + 8] = o01;
    out4[r1 * 16 + lane8    ] = o10;
    out4[r1 * 16 + lane8 + 8] = o11;
}

extern "C" void kernel_launch(void* const* d_in, const int* in_sizes, int n_in,
                              void* d_out, int out_size)
{
    const float* q   = (const float*)d_in[0];
    const float* k   = (const float*)d_in[1];
    const float* v   = (const float*)d_in[2];
    const float* kpm = (const float*)d_in[3];
    const int* layout = (const int*)d_in[4];
    float* out = (float*)d_out;

    dim3 grid(NB, HEADS, 2);   // (q block, head, batch)
    dim3 block(128);
    sparse_attn_kernel<<<grid, block>>>(q, k, v, kpm, layout, out);
}

// round 2
// speedup vs baseline: 2.7064x; 2.7064x over previous
#include <cuda_runtime.h>
#include <math_constants.h>

// SparseSelfAttention: B=2,H=16,L=2048,D=64,BLK=32,NB=64 (causal local band, window=8)
// mma.sync tf32 flash-attention. CTA = 128 thr = 4 warps = 64 q rows (2 q-blocks).
// Each warp owns 16 q rows (m16). QK^T and PV via mma.m16n8k8.tf32.

#define HEADS 16
#define SEQ   2048
#define DIM   64
#define NB    64
#define BLK   32

#define KSTR  72   // u32 row stride for K/V smem (conflict-free frag loads)
#define PSTR  36   // u32 row stride for P smem
#define QSTR  68   // u32 row stride for Q staging

__device__ __forceinline__ unsigned f2tf32(float f) {
    unsigned r;
    asm("cvt.rna.tf32.f32 %0, %1;" : "=r"(r) : "f"(f));
    return r;
}

__device__ __forceinline__ void mma_tf32(float c[4], const unsigned a[4], const unsigned b[2]) {
    asm volatile("mma.sync.aligned.m16n8k8.row.col.f32.tf32.tf32.f32 "
                 "{%0,%1,%2,%3}, {%4,%5,%6,%7}, {%8,%9}, {%0,%1,%2,%3};"
                 : "+f"(c[0]), "+f"(c[1]), "+f"(c[2]), "+f"(c[3])
                 : "r"(a[0]), "r"(a[1]), "r"(a[2]), "r"(a[3]),
                   "r"(b[0]), "r"(b[1]));
}

__global__ __launch_bounds__(128, 2)
void sparse_attn_tc(const float* __restrict__ qg,
                    const float* __restrict__ kg,
                    const float* __restrict__ vg,
                    const float* __restrict__ kpm,
                    const int*   __restrict__ layout,
                    float* __restrict__ outg)
{
    __shared__ __align__(16) union {
        struct { unsigned K[BLK * KSTR]; unsigned V[BLK * KSTR]; } kv;
        unsigned qstage[64 * QSTR];
    } sm;
    __shared__ float    kpms[BLK];
    __shared__ unsigned Ps[64 * PSTR];   // per-warp 16-row slices
    __shared__ int      layA[NB], layB[NB];

    const int tid  = threadIdx.x;
    const int w    = tid >> 5;
    const int lane = tid & 31;
    const int gid  = lane >> 2;  // 0..7
    const int t4   = lane & 3;   // 0..3

    const int i2 = blockIdx.x;   // pair of q-blocks: rows [i2*64, i2*64+64)
    const int h  = blockIdx.y;
    const int b  = blockIdx.z;

    const size_t bh = (size_t)b * HEADS + h;
    const float* kbase = kg + bh * SEQ * DIM;
    const float* vbase = vg + bh * SEQ * DIM;

    // layout rows for both q-blocks
    if (tid < NB)       layA[tid]      = layout[((size_t)h * NB + i2 * 2    ) * NB + tid];
    else                layB[tid - NB] = layout[((size_t)h * NB + i2 * 2 + 1) * NB + tid - NB];

    // ---- stage Q (pre-scaled, tf32) ----
    const float* qptr = qg + (bh * SEQ + (size_t)i2 * 64) * DIM;
    #pragma unroll
    for (int jj = 0; jj < 8; jj++) {
        int idx = tid + 128 * jj;         // 1024 float4 total
        int row = idx >> 4, d4 = idx & 15;
        float4 qv = reinterpret_cast<const float4*>(qptr)[idx];
        uint4 t;
        t.x = f2tf32(qv.x * 0.125f); t.y = f2tf32(qv.y * 0.125f);
        t.z = f2tf32(qv.z * 0.125f); t.w = f2tf32(qv.w * 0.125f);
        *reinterpret_cast<uint4*>(&sm.qstage[row * QSTR + d4 * 4]) = t;
    }
    __syncthreads();

    // ---- Q A-fragments in registers for whole kernel ----
    const int lrow = w * 16 + gid;        // local row within CTA's 64 rows
    unsigned qa[8][4];
    #pragma unroll
    for (int kst = 0; kst < 8; kst++) {
        qa[kst][0] = sm.qstage[ lrow      * QSTR + kst * 8 + t4    ];
        qa[kst][1] = sm.qstage[(lrow + 8) * QSTR + kst * 8 + t4    ];
        qa[kst][2] = sm.qstage[ lrow      * QSTR + kst * 8 + t4 + 4];
        qa[kst][3] = sm.qstage[(lrow + 8) * QSTR + kst * 8 + t4 + 4];
    }
    __syncthreads();   // qstage dead; kv union takes over

    const int* layw = (w & 2) ? layB : layA;

    float m_lo = -CUDART_INF_F, m_hi = -CUDART_INF_F;
    float l_lo = 0.f, l_hi = 0.f;
    float o[8][4];
    #pragma unroll
    for (int n = 0; n < 8; n++) { o[n][0]=0.f; o[n][1]=0.f; o[n][2]=0.f; o[n][3]=0.f; }

    for (int j = 0; j < NB; j++) {
        if (!(layA[j] | layB[j])) continue;   // uniform across CTA

        // ---- stage K/V block j as tf32 ----
        const float* kp = kbase + (size_t)j * BLK * DIM;
        const float* vp = vbase + (size_t)j * BLK * DIM;
        #pragma unroll
        for (int jj = 0; jj < 4; jj++) {
            int idx = tid + 128 * jj;       // 512 float4
            int row = idx >> 4, d4 = idx & 15;
            float4 kv4 = reinterpret_cast<const float4*>(kp)[idx];
            float4 vv4 = reinterpret_cast<const float4*>(vp)[idx];
            uint4 tk, tv;
            tk.x = f2tf32(kv4.x); tk.y = f2tf32(kv4.y); tk.z = f2tf32(kv4.z); tk.w = f2tf32(kv4.w);
            tv.x = f2tf32(vv4.x); tv.y = f2tf32(vv4.y); tv.z = f2tf32(vv4.z); tv.w = f2tf32(vv4.w);
            *reinterpret_cast<uint4*>(&sm.kv.K[row * KSTR + d4 * 4]) = tk;
            *reinterpret_cast<uint4*>(&sm.kv.V[row * KSTR + d4 * 4]) = tv;
        }
        if (tid < BLK) kpms[tid] = kpm[(size_t)b * SEQ + j * BLK + tid];
        __syncthreads();

        if (layw[j]) {
            // ---- QK^T: 16x32 scores per warp ----
            float s[4][4];
            #pragma unroll
            for (int nt = 0; nt < 4; nt++) {
                float c[4] = {0.f, 0.f, 0.f, 0.f};
                #pragma unroll
                for (int kst = 0; kst < 8; kst++) {
                    unsigned bf[2];
                    bf[0] = sm.kv.K[(nt * 8 + gid) * KSTR + kst * 8 + t4    ];
                    bf[1] = sm.kv.K[(nt * 8 + gid) * KSTR + kst * 8 + t4 + 4];
                    mma_tf32(c, qa[kst], bf);
                }
                float2 kb = *reinterpret_cast<const float2*>(&kpms[nt * 8 + 2 * t4]);
                s[nt][0] = c[0] + kb.x; s[nt][1] = c[1] + kb.y;   // row gid
                s[nt][2] = c[2] + kb.x; s[nt][3] = c[3] + kb.y;   // row gid+8
            }

            // ---- online softmax (2 rows per lane-group) ----
            float bx_lo = fmaxf(fmaxf(s[0][0], s[0][1]), fmaxf(s[1][0], s[1][1]));
            bx_lo = fmaxf(bx_lo, fmaxf(fmaxf(s[2][0], s[2][1]), fmaxf(s[3][0], s[3][1])));
            float bx_hi = fmaxf(fmaxf(s[0][2], s[0][3]), fmaxf(s[1][2], s[1][3]));
            bx_hi = fmaxf(bx_hi, fmaxf(fmaxf(s[2][2], s[2][3]), fmaxf(s[3][2], s[3][3])));
            #pragma unroll
            for (int off = 1; off < 4; off <<= 1) {
                bx_lo = fmaxf(bx_lo, __shfl_xor_sync(0xffffffffu, bx_lo, off));
                bx_hi = fmaxf(bx_hi, __shfl_xor_sync(0xffffffffu, bx_hi, off));
            }
            float mn_lo = fmaxf(m_lo, bx_lo);
            float mn_hi = fmaxf(m_hi, bx_hi);
            float a_lo = __expf(m_lo - mn_lo);
            float a_hi = __expf(m_hi - mn_hi);
            m_lo = mn_lo; m_hi = mn_hi;

            float sum_lo = 0.f, sum_hi = 0.f;
            const int prow = w * 16 + gid;
            #pragma unroll
            for (int nt = 0; nt < 4; nt++) {
                float p0 = __expf(s[nt][0] - m_lo);
                float p1 = __expf(s[nt][1] - m_lo);
                float p2 = __expf(s[nt][2] - m_hi);
                float p3 = __expf(s[nt][3] - m_hi);
                sum_lo += p0 + p1;
                sum_hi += p2 + p3;
                uint2 plo, phi;
                plo.x = f2tf32(p0); plo.y = f2tf32(p1);
                phi.x = f2tf32(p2); phi.y = f2tf32(p3);
                *reinterpret_cast<uint2*>(&Ps[ prow      * PSTR + nt * 8 + 2 * t4]) = plo;
                *reinterpret_cast<uint2*>(&Ps[(prow + 8) * PSTR + nt * 8 + 2 * t4]) = phi;
            }
            #pragma unroll
            for (int off = 1; off < 4; off <<= 1) {
                sum_lo += __shfl_xor_sync(0xffffffffu, sum_lo, off);
                sum_hi += __shfl_xor_sync(0xffffffffu, sum_hi, off);
            }
            l_lo = l_lo * a_lo + sum_lo;
            l_hi = l_hi * a_hi + sum_hi;

            // rescale output accumulators
            #pragma unroll
            for (int n = 0; n < 8; n++) {
                o[n][0] *= a_lo; o[n][1] *= a_lo;
                o[n][2] *= a_hi; o[n][3] *= a_hi;
            }
            __syncwarp();

            // ---- P A-fragments ----
            unsigned pa[4][4];
            #pragma unroll
            for (int kst = 0; kst < 4; kst++) {
                pa[kst][0] = Ps[ prow      * PSTR + kst * 8 + t4    ];
                pa[kst][1] = Ps[(prow + 8) * PSTR + kst * 8 + t4    ];
                pa[kst][2] = Ps[ prow      * PSTR + kst * 8 + t4 + 4];
                pa[kst][3] = Ps[(prow + 8) * PSTR + kst * 8 + t4 + 4];
            }

            // ---- PV: o += P @ V ----
            #pragma unroll
            for (int nt2 = 0; nt2 < 8; nt2++) {
                #pragma unroll
                for (int kst = 0; kst < 4; kst++) {
                    unsigned bf[2];
                    bf[0] = sm.kv.V[(kst * 8 + t4    ) * KSTR + nt2 * 8 + gid];
                    bf[1] = sm.kv.V[(kst * 8 + t4 + 4) * KSTR + nt2 * 8 + gid];
                    mma_tf32(o[nt2], pa[kst], bf);
                }
            }
        }
        __syncthreads();   // protect kv/kpms before next stage
    }

    // ---- epilogue: normalize + store ----
    float inv_lo = 1.0f / l_lo;
    float inv_hi = 1.0f / l_hi;
    float* op = outg + (bh * SEQ + (size_t)i2 * 64) * DIM;
    #pragma unroll
    for (int nt2 = 0; nt2 < 8; nt2++) {
        float2 vlo, vhi;
        vlo.x = o[nt2][0] * inv_lo; vlo.y = o[nt2][1] * inv_lo;
        vhi.x = o[nt2][2] * inv_hi; vhi.y = o[nt2][3] * inv_hi;
        reinterpret_cast<float2*>(op +  lrow      * DIM)[nt2 * 4 + t4] = vlo;
        reinterpret_cast<float2*>(op + (lrow + 8) * DIM)[nt2 * 4 + t4] = vhi;
    }
}

extern "C" void kernel_launch(void* const* d_in, const int* in_sizes, int n_in,
                              void* d_out, int out_size)
{
    const float* q   = (const float*)d_in[0];
    const float* k   = (const float*)d_in[1];
    const float* v   = (const float*)d_in[2];
    const float* kpm = (const float*)d_in[3];
    const int* layout = (const int*)d_in[4];
    float* out = (float*)d_out;

    dim3 grid(NB / 2, HEADS, 2);   // (q-block pair, head, batch)
    dim3 block(128);
    sparse_attn_tc<<<grid, block>>>(q, k, v, kpm, layout, out);
}

// round 4
// speedup vs baseline: 2.7182x; 1.0044x over previous
#include <cuda_runtime.h>
#include <math_constants.h>

// SparseSelfAttention: B=2,H=16,L=2048,D=64,BLK=32,NB=64 (causal local band, window=8)
// tf32 mma.sync flash-attention with cp.async double-buffered KV pipeline.
// CTA = 128 thr = 4 warps = 64 q rows (2 q-blocks). Warp owns 16 q rows.

#define HEADS 16
#define SEQ   2048
#define DIM   64
#define NB    64
#define BLK   32

#define NSTR  72   // float row stride for K/V stages (conflict-free both frag patterns)
#define PSTR  36
#define QSTR  68

__device__ __forceinline__ unsigned f2tf32(float f) {
    unsigned r;
    asm("cvt.rna.tf32.f32 %0, %1;" : "=r"(r) : "f"(f));
    return r;
}

__device__ __forceinline__ void mma_tf32(float c[4], const unsigned a[4], const unsigned b[2]) {
    asm volatile("mma.sync.aligned.m16n8k8.row.col.f32.tf32.tf32.f32 "
                 "{%0,%1,%2,%3}, {%4,%5,%6,%7}, {%8,%9}, {%0,%1,%2,%3};"
                 : "+f"(c[0]), "+f"(c[1]), "+f"(c[2]), "+f"(c[3])
                 : "r"(a[0]), "r"(a[1]), "r"(a[2]), "r"(a[3]),
                   "r"(b[0]), "r"(b[1]));
}

__device__ __forceinline__ unsigned smem_addr_u32(const void* p) {
    unsigned a;
    asm("{ .reg .u64 t; cvta.to.shared.u64 t, %1; cvt.u32.u64 %0, t; }" : "=r"(a) : "l"(p));
    return a;
}

__device__ __forceinline__ void cp16(unsigned dst, const void* src) {
    asm volatile("cp.async.ca.shared.global [%0], [%1], 16;\n" :: "r"(dst), "l"(src));
}

__global__ __launch_bounds__(128, 3)
void sparse_attn_tc(const float* __restrict__ qg,
                    const float* __restrict__ kg,
                    const float* __restrict__ vg,
                    const float* __restrict__ kpm,
                    const int*   __restrict__ layout,
                    float* __restrict__ outg)
{
    // [stage][K=0/V=1][32 rows * NSTR]; stage-1 region doubles as Q staging.
    __shared__ __align__(16) float SKV[2][2][BLK * NSTR];   // 36864 B
    __shared__ __align__(16) float kpms2[2][BLK];
    __shared__ unsigned Ps[64 * PSTR];                      // 9216 B
    __shared__ int layA[NB], layB[NB];
    __shared__ int jlist[NB];
    __shared__ int jcnt;

    const int tid  = threadIdx.x;
    const int w    = tid >> 5;
    const int lane = tid & 31;
    const int gid  = lane >> 2;
    const int t4   = lane & 3;

    const int i2 = blockIdx.x;
    const int h  = blockIdx.y;
    const int b  = blockIdx.z;

    const size_t bh = (size_t)b * HEADS + h;
    const float* kbase = kg + bh * SEQ * DIM;
    const float* vbase = vg + bh * SEQ * DIM;

    if (tid < NB)       layA[tid]      = layout[((size_t)h * NB + i2 * 2    ) * NB + tid];
    else                layB[tid - NB] = layout[((size_t)h * NB + i2 * 2 + 1) * NB + tid - NB];

    // ---- stage Q (tf32, pre-scaled) into stage-1 region ----
    unsigned* qstage = reinterpret_cast<unsigned*>(&SKV[1][0][0]);   // 64*QSTR u32 fits
    const float* qptr = qg + (bh * SEQ + (size_t)i2 * 64) * DIM;
    #pragma unroll
    for (int jj = 0; jj < 8; jj++) {
        int idx = tid + 128 * jj;
        int row = idx >> 4, d4 = idx & 15;
        float4 qv = reinterpret_cast<const float4*>(qptr)[idx];
        uint4 t;
        t.x = f2tf32(qv.x * 0.125f); t.y = f2tf32(qv.y * 0.125f);
        t.z = f2tf32(qv.z * 0.125f); t.w = f2tf32(qv.w * 0.125f);
        *reinterpret_cast<uint4*>(&qstage[row * QSTR + d4 * 4]) = t;
    }
    __syncthreads();

    // compact active-block list (union of both q-block rows)
    if (tid == 0) {
        int c = 0;
        for (int j = 0; j < NB; j++) if (layA[j] | layB[j]) jlist[c++] = j;
        jcnt = c;
    }

    // Q A-fragments in registers for the whole kernel
    const int lrow = w * 16 + gid;
    unsigned qa[8][4];
    #pragma unroll
    for (int kst = 0; kst < 8; kst++) {
        qa[kst][0] = qstage[ lrow      * QSTR + kst * 8 + t4    ];
        qa[kst][1] = qstage[(lrow + 8) * QSTR + kst * 8 + t4    ];
        qa[kst][2] = qstage[ lrow      * QSTR + kst * 8 + t4 + 4];
        qa[kst][3] = qstage[(lrow + 8) * QSTR + kst * 8 + t4 + 4];
    }
    __syncthreads();   // jlist visible; qstage dead (stage-1 free)

    const int nj = jcnt;
    const int* layw = (w & 2) ? layB : layA;

    const unsigned skv_base  = smem_addr_u32(&SKV[0][0][0]);
    const unsigned kpms_base = smem_addr_u32(&kpms2[0][0]);
    const int krow = tid >> 4, kc = tid & 15;   // this thread's 4 cp.async chunks per array

    // prologue: stage block jlist[0] into stage 0
    {
        int j0 = jlist[0];
        const float* kp = kbase + (size_t)j0 * BLK * DIM;
        const float* vp = vbase + (size_t)j0 * BLK * DIM;
        #pragma unroll
        for (int jj = 0; jj < 4; jj++) {
            int idx = tid + 128 * jj;
            int row = idx >> 4, c = idx & 15;
            cp16(skv_base + (unsigned)((0 * BLK * NSTR + row * NSTR + c * 4) * 4), kp + row * DIM + c * 4);
            cp16(skv_base + (unsigned)((1 * BLK * NSTR + row * NSTR + c * 4) * 4), vp + row * DIM + c * 4);
        }
        if (tid < 8) cp16(kpms_base + tid * 16, kpm + (size_t)b * SEQ + j0 * BLK + tid * 4);
        asm volatile("cp.async.commit_group;\n" ::);
        asm volatile("cp.async.wait_group 0;\n" ::);
    }
    __syncthreads();

    float m_lo = -CUDART_INF_F, m_hi = -CUDART_INF_F;
    float l_lo = 0.f, l_hi = 0.f;
    float o[8][4];
    #pragma unroll
    for (int n = 0; n < 8; n++) { o[n][0]=0.f; o[n][1]=0.f; o[n][2]=0.f; o[n][3]=0.f; }

    for (int idx = 0; idx < nj; idx++) {
        const int s = idx & 1;

        // prefetch next active block into stage s^1
        if (idx + 1 < nj) {
            int jn = jlist[idx + 1];
            const float* kp = kbase + (size_t)jn * BLK * DIM;
            const float* vp = vbase + (size_t)jn * BLK * DIM;
            unsigned so = (unsigned)((s ^ 1) * 2 * BLK * NSTR * 4);
            #pragma unroll
            for (int jj = 0; jj < 4; jj++) {
                int ii = tid + 128 * jj;
                int row = ii >> 4, c = ii & 15;
                cp16(skv_base + so + (unsigned)((row * NSTR + c * 4) * 4),                  kp + row * DIM + c * 4);
                cp16(skv_base + so + (unsigned)((BLK * NSTR + row * NSTR + c * 4) * 4),    vp + row * DIM + c * 4);
            }
            if (tid < 8) cp16(kpms_base + (unsigned)((s ^ 1) * BLK * 4) + tid * 16,
                              kpm + (size_t)b * SEQ + jn * BLK + tid * 4);
        }
        asm volatile("cp.async.commit_group;\n" ::);

        const int j = jlist[idx];
        if (layw[j]) {
            const float* Ksm = &SKV[s][0][0];
            const float* Vsm = &SKV[s][1][0];
            const float* kpv = &kpms2[s][0];

            // ---- QK^T ----
            float sc[4][4];
            #pragma unroll
            for (int nt = 0; nt < 4; nt++) {
                float c[4] = {0.f, 0.f, 0.f, 0.f};
                #pragma unroll
                for (int kst = 0; kst < 8; kst++) {
                    unsigned bf[2];
                    bf[0] = f2tf32(Ksm[(nt * 8 + gid) * NSTR + kst * 8 + t4    ]);
                    bf[1] = f2tf32(Ksm[(nt * 8 + gid) * NSTR + kst * 8 + t4 + 4]);
                    mma_tf32(c, qa[kst], bf);
                }
                float2 kb = *reinterpret_cast<const float2*>(&kpv[nt * 8 + 2 * t4]);
                sc[nt][0] = c[0] + kb.x; sc[nt][1] = c[1] + kb.y;
                sc[nt][2] = c[2] + kb.x; sc[nt][3] = c[3] + kb.y;
            }

            // ---- online softmax ----
            float bx_lo = fmaxf(fmaxf(sc[0][0], sc[0][1]), fmaxf(sc[1][0], sc[1][1]));
            bx_lo = fmaxf(bx_lo, fmaxf(fmaxf(sc[2][0], sc[2][1]), fmaxf(sc[3][0], sc[3][1])));
            float bx_hi = fmaxf(fmaxf(sc[0][2], sc[0][3]), fmaxf(sc[1][2], sc[1][3]));
            bx_hi = fmaxf(bx_hi, fmaxf(fmaxf(sc[2][2], sc[2][3]), fmaxf(sc[3][2], sc[3][3])));
            #pragma unroll
            for (int off = 1; off < 4; off <<= 1) {
                bx_lo = fmaxf(bx_lo, __shfl_xor_sync(0xffffffffu, bx_lo, off));
                bx_hi = fmaxf(bx_hi, __shfl_xor_sync(0xffffffffu, bx_hi, off));
            }
            float mn_lo = fmaxf(m_lo, bx_lo);
            float mn_hi = fmaxf(m_hi, bx_hi);
            float a_lo = __expf(m_lo - mn_lo);
            float a_hi = __expf(m_hi - mn_hi);
            m_lo = mn_lo; m_hi = mn_hi;

            float sum_lo = 0.f, sum_hi = 0.f;
            const int prow = w * 16 + gid;
            #pragma unroll
            for (int nt = 0; nt < 4; nt++) {
                float p0 = __expf(sc[nt][0] - m_lo);
                float p1 = __expf(sc[nt][1] - m_lo);
                float p2 = __expf(sc[nt][2] - m_hi);
                float p3 = __expf(sc[nt][3] - m_hi);
                sum_lo += p0 + p1;
                sum_hi += p2 + p3;
                uint2 plo, phi;
                plo.x = f2tf32(p0); plo.y = f2tf32(p1);
                phi.x = f2tf32(p2); phi.y = f2tf32(p3);
                *reinterpret_cast<uint2*>(&Ps[ prow      * PSTR + nt * 8 + 2 * t4]) = plo;
                *reinterpret_cast<uint2*>(&Ps[(prow + 8) * PSTR + nt * 8 + 2 * t4]) = phi;
            }
            #pragma unroll
            for (int off = 1; off < 4; off <<= 1) {
                sum_lo += __shfl_xor_sync(0xffffffffu, sum_lo, off);
                sum_hi += __shfl_xor_sync(0xffffffffu, sum_hi, off);
            }
            l_lo = l_lo * a_lo + sum_lo;
            l_hi = l_hi * a_hi + sum_hi;

            #pragma unroll
            for (int n = 0; n < 8; n++) {
                o[n][0] *= a_lo; o[n][1] *= a_lo;
                o[n][2] *= a_hi; o[n][3] *= a_hi;
            }
            __syncwarp();

            // ---- P A-fragments ----
            unsigned pa[4][4];
            #pragma unroll
            for (int kst = 0; kst < 4; kst++) {
                pa[kst][0] = Ps[ prow      * PSTR + kst * 8 + t4    ];
                pa[kst][1] = Ps[(prow + 8) * PSTR + kst * 8 + t4    ];
                pa[kst][2] = Ps[ prow      * PSTR + kst * 8 + t4 + 4];
                pa[kst][3] = Ps[(prow + 8) * PSTR + kst * 8 + t4 + 4];
            }

            // ---- PV ----
            #pragma unroll
            for (int nt2 = 0; nt2 < 8; nt2++) {
                #pragma unroll
                for (int kst = 0; kst < 4; kst++) {
                    unsigned bf[2];
                    bf[0] = f2tf32(Vsm[(kst * 8 + t4    ) * NSTR + nt2 * 8 + gid]);
                    bf[1] = f2tf32(Vsm[(kst * 8 + t4 + 4) * NSTR + nt2 * 8 + gid]);
                    mma_tf32(o[nt2], pa[kst], bf);
                }
            }
        }

        asm volatile("cp.async.wait_group 0;\n" ::);
        __syncthreads();
    }

    // ---- epilogue ----
    float inv_lo = 1.0f / l_lo;
    float inv_hi = 1.0f / l_hi;
    float* op = outg + (bh * SEQ + (size_t)i2 * 64) * DIM;
    #pragma unroll
    for (int nt2 = 0; nt2 < 8; nt2++) {
        float2 vlo, vhi;
        vlo.x = o[nt2][0] * inv_lo; vlo.y = o[nt2][1] * inv_lo;
        vhi.x = o[nt2][2] * inv_hi; vhi.y = o[nt2][3] * inv_hi;
        reinterpret_cast<float2*>(op +  lrow      * DIM)[nt2 * 4 + t4] = vlo;
        reinterpret_cast<float2*>(op + (lrow + 8) * DIM)[nt2 * 4 + t4] = vhi;
    }
}

extern "C" void kernel_launch(void* const* d_in, const int* in_sizes, int n_in,
                              void* d_out, int out_size)
{
    const float* q   = (const float*)d_in[0];
    const float* k   = (const float*)d_in[1];
    const float* v   = (const float*)d_in[2];
    const float* kpm = (const float*)d_in[3];
    const int* layout = (const int*)d_in[4];
    float* out = (float*)d_out;

    dim3 grid(NB / 2, HEADS, 2);
    dim3 block(128);
    sparse_attn_tc<<<grid, block>>>(q, k, v, kpm, layout, out);
}